// round 15
// baseline (speedup 1.0000x reference)
#include <cuda_runtime.h>
#include <cuda_bf16.h>
#include <cstdint>

// Problem constants (shapes fixed by setup_inputs)
#define BSZ   4
#define LSZ   2048
#define KNB   30      // TOP_K
#define NRB   256     // 16 banks * 16 rbf channels (positional via table)
#define NOUT  128
#define MAXREL 32
#define NDC   66      // dcode values: 0..64 same-chain, 65 cross-chain
#define NEDGE (BSZ*LSZ*KNB)     // 245760
#define MTILES (NEDGE/128)      // 1920 (exact)
#define ASTRIDE 72              // smem A row stride in bf16 (144B, 16B-aligned)
#define NBUCK 2048              // topk histogram buckets (float bits >> 20)
#define CAP   512               // candidate buffer bound

// -------- device scratch (no cudaMalloc allowed) --------
__device__ float    g_Cb  [BSZ*LSZ*3];
__device__ float4   g_C4  [BSZ*LSZ];           // (Cx,Cy,Cz,mask) packed
__device__ int      g_Eidx[NEDGE];
__device__ float    g_Dsel[NEDGE];
__device__ int      g_Dcode[NEDGE];
__device__ float    g_Tpos[NDC*NOUT];          // (W_pos[d]+b_pos) @ W_edge[0:16]
__device__ uint32_t g_Fh[(size_t)NEDGE*128];   // features hi, bf16x2 pairs
__device__ uint32_t g_Fl[(size_t)NEDGE*128];   // features lo
__device__ uint2    g_WfH[16*16*32];           // W hi, B-fragment layout [ks][nf][lane]
__device__ uint2    g_WfL[16*16*32];           // W lo

// pair tables: dist(A_atom of residue i, B_atom of residue j)
// atom codes: 0=N, 1=C, 2=Ca, 3=Cb(virtual)
__constant__ int c_PA[15] = {0,2,3,1,1,1,0,0,3,0,2,3,2,3,2};
__constant__ int c_PB[15] = {0,2,3,0,2,3,2,3,2,1,1,1,0,0,3};

// ---------- helpers ----------
__device__ __forceinline__ uint32_t pack_bf16x2(__nv_bfloat16 lo, __nv_bfloat16 hi) {
    uint32_t l = (uint32_t)__bfloat16_as_ushort(lo);
    uint32_t h = (uint32_t)__bfloat16_as_ushort(hi);
    return l | (h << 16);
}
__device__ __forceinline__ uint32_t smem_to_u32(const void* p) {
    uint32_t a;
    asm("{ .reg .u64 t; cvta.to.shared.u64 t, %1; cvt.u32.u64 %0, t; }"
        : "=r"(a) : "l"(p));
    return a;
}
__device__ __forceinline__ void ldsm_x4(uint32_t* r, uint32_t addr) {
    asm volatile("ldmatrix.sync.aligned.m8n8.x4.shared.b16 {%0,%1,%2,%3}, [%4];"
        : "=r"(r[0]), "=r"(r[1]), "=r"(r[2]), "=r"(r[3]) : "r"(addr));
}
__device__ __forceinline__ void mma_bf16(float* c, const uint32_t* a,
                                         const uint32_t* b) {
    asm volatile(
        "mma.sync.aligned.m16n8k16.row.col.f32.bf16.bf16.f32 "
        "{%0,%1,%2,%3}, {%4,%5,%6,%7}, {%8,%9}, {%0,%1,%2,%3};"
        : "+f"(c[0]), "+f"(c[1]), "+f"(c[2]), "+f"(c[3])
        : "r"(a[0]), "r"(a[1]), "r"(a[2]), "r"(a[3]), "r"(b[0]), "r"(b[1]));
}
// exp(-u), u >= 0, FMA/ALU pipes only (no MUFU). ~1e-7 rel.
__device__ __forceinline__ float exp_neg(float u) {
    float t = fmaxf(-u * 1.4426950408889634f, -150.0f);
    float k = rintf(t);
    float f = t - k;
    float p =        1.5403530393e-4f;
    p = fmaf(p, f, 1.3333558146e-3f);
    p = fmaf(p, f, 9.6181291076e-3f);
    p = fmaf(p, f, 5.5504108665e-2f);
    p = fmaf(p, f, 2.4022650696e-1f);
    p = fmaf(p, f, 6.9314718056e-1f);
    p = fmaf(p, f, 1.0f);
    int ki = (int)k;
    int k1 = ki >> 1, k2 = ki - k1;        // two-step scale, no underflow wrap
    float s1 = __int_as_float((k1 + 127) << 23);
    float s2 = __int_as_float((k2 + 127) << 23);
    return p * s1 * s2;
}

// ============================================================
// Kernel 0a: positional projection table
// ============================================================
__global__ void tpos_kernel(const float* __restrict__ W_pos,
                            const float* __restrict__ b_pos,
                            const float* __restrict__ W_edge)
{
    int d = blockIdx.x, t = threadIdx.x;
    float acc = 0.f;
    #pragma unroll
    for (int f = 0; f < 16; f++)
        acc = fmaf(W_pos[d*16 + f] + b_pos[f], W_edge[f*NOUT + t], acc);
    g_Tpos[d*NOUT + t] = acc;
}

// Kernel 0b: W -> bf16 hi/lo in exact mma.sync B-fragment order.
__global__ void wprep_kernel(const float* __restrict__ W_edge)
{
    int idx = blockIdx.x*256 + threadIdx.x;      // 8192 frags
    int lane = idx & 31, nfg = (idx >> 5) & 15, ks = idx >> 9;
    int n = nfg*8 + (lane >> 2);
    int k = ks*16 + 2*(lane & 3);
    float w[4];
    w[0] = W_edge[(16 + k    )*NOUT + n];
    w[1] = W_edge[(16 + k + 1)*NOUT + n];
    w[2] = W_edge[(16 + k + 8)*NOUT + n];
    w[3] = W_edge[(16 + k + 9)*NOUT + n];
    __nv_bfloat16 h[4]; float l[4];
    #pragma unroll
    for (int i = 0; i < 4; i++) {
        h[i] = __float2bfloat16(w[i]);
        l[i] = w[i] - __bfloat162float(h[i]);
    }
    uint2 uh, ul;
    uh.x = pack_bf16x2(h[0], h[1]);
    uh.y = pack_bf16x2(h[2], h[3]);
    ul.x = pack_bf16x2(__float2bfloat16(l[0]), __float2bfloat16(l[1]));
    ul.y = pack_bf16x2(__float2bfloat16(l[2]), __float2bfloat16(l[3]));
    g_WfH[idx] = uh;
    g_WfL[idx] = ul;
}

// ============================================================
// Kernel 1: virtual C-beta + packed (C,mask) float4
// ============================================================
__global__ void cb_kernel(const float* __restrict__ X,
                          const float* __restrict__ mask)
{
    int i = blockIdx.x * 256 + threadIdx.x;
    if (i >= BSZ*LSZ) return;
    const float* x = &X[i*12];
    float Nx=x[0],  Ny=x[1],  Nz=x[2];
    float Cx=x[3],  Cy=x[4],  Cz=x[5];
    float Ax=x[6],  Ay=x[7],  Az=x[8];
    float bx=Ax-Nx, by=Ay-Ny, bz=Az-Nz;
    float cx=Cx-Ax, cy=Cy-Ay, cz=Cz-Az;
    float ax = by*cz - bz*cy;
    float ay = bz*cx - bx*cz;
    float az = bx*cy - by*cx;
    g_Cb[i*3+0] = -0.58273431f*ax + 0.56802827f*bx - 0.54067466f*cx + Ax;
    g_Cb[i*3+1] = -0.58273431f*ay + 0.56802827f*by - 0.54067466f*cy + Ay;
    g_Cb[i*3+2] = -0.58273431f*az + 0.56802827f*bz - 0.54067466f*cz + Az;
    g_C4[i] = make_float4(Cx, Cy, Cz, mask[i]);
}

// ============================================================
// Kernel 2: masked pairwise C-C distances + EXACT top-30 via
// histogram select + PARALLEL RANK placement.
// Histogram adds are WARP-AGGREGATED (__match_any_sync): distances
// cluster into ~56 hot buckets, so raw per-lane ATOMS serialize
// ~4-8x; electing one leader per equal-bucket group removes that.
// Candidate compaction uses one ballot-scan atomic per warp.
// ============================================================
__global__ __launch_bounds__(256) void topk_kernel(float* __restrict__ outIdxF)
{
    int row = blockIdx.x;
    int b   = row / LSZ;
    int t   = threadIdx.x;
    int warp = t >> 5, lane = t & 31;
    unsigned lmask_lt = (lane == 0) ? 0u : (0xffffffffu >> (32 - lane));

    __shared__ float wmax[8];
    __shared__ float sDmax;
    __shared__ uint32_t hist[NBUCK];
    __shared__ int sB;
    __shared__ int scnt;
    __shared__ unsigned long long cand[CAP];

    float4 me = g_C4[row];
    float mi = me.w;

    float dv[8], m2v[8];
    float lmax = 0.f;
    #pragma unroll
    for (int r = 0; r < 8; r++) {
        int j = t + r*256;
        float4 pj = g_C4[b*LSZ + j];
        float dx = me.x-pj.x, dy = me.y-pj.y, dz = me.z-pj.z;
        float d  = sqrtf(dx*dx + dy*dy + dz*dz + 1e-6f);
        float m2 = mi * pj.w;
        dv[r]  = m2 * d;
        m2v[r] = m2;
        lmax = fmaxf(lmax, dv[r]);
    }
    #pragma unroll
    for (int o = 16; o > 0; o >>= 1)
        lmax = fmaxf(lmax, __shfl_xor_sync(0xffffffffu, lmax, o));
    if (lane == 0) wmax[warp] = lmax;
    // zero histogram + counter while the max reduction settles
    #pragma unroll
    for (int h = 0; h < NBUCK/256; h++) hist[t + h*256] = 0;
    if (t == 0) scnt = 0;
    __syncthreads();
    if (t == 0) {
        float m = wmax[0];
        for (int w = 1; w < 8; w++) m = fmaxf(m, wmax[w]);
        sDmax = m;
    }
    __syncthreads();
    float Dmax = sDmax;

    unsigned long long key[8];
    #pragma unroll
    for (int r = 0; r < 8; r++) {
        float adj = dv[r] + (1.0f - m2v[r]) * Dmax;      // D_adjust
        key[r] = ((unsigned long long)__float_as_uint(adj) << 32)
               | (unsigned)(t + r*256);
        unsigned bk = (unsigned)(key[r] >> 52);
        unsigned grp = __match_any_sync(0xffffffffu, bk);
        if ((grp & lmask_lt) == 0)               // lowest lane of equal-bucket group
            atomicAdd(&hist[bk], (uint32_t)__popc(grp));
    }
    __syncthreads();

    // warp 0: find threshold bucket B (cum count reaches KNB)
    if (warp == 0) {
        int base = lane * (NBUCK/32);
        int s = 0;
        #pragma unroll 8
        for (int c = 0; c < NBUCK/32; c++) s += (int)hist[base + c];
        int pre = s;
        #pragma unroll
        for (int o = 1; o < 32; o <<= 1) {
            int v = __shfl_up_sync(0xffffffffu, pre, o);
            if (lane >= o) pre += v;
        }
        pre -= s;                         // exclusive prefix
        if (pre < KNB && pre + s >= KNB) {
            int acc = pre, Bq = base + NBUCK/32 - 1;
            for (int c = 0; c < NBUCK/32; c++) {
                acc += (int)hist[base + c];
                if (acc >= KNB) { Bq = base + c; break; }
            }
            sB = Bq;
        }
    }
    __syncthreads();

    // compact candidates: ballot-scan, one atomic per warp per round
    int B = sB;
    #pragma unroll
    for (int r = 0; r < 8; r++) {
        bool p = ((int)(unsigned)(key[r] >> 52) <= B);
        unsigned m = __ballot_sync(0xffffffffu, p);
        if (m) {
            int base_pos = 0;
            if (lane == __ffs(m) - 1)
                base_pos = atomicAdd(&scnt, __popc(m));
            base_pos = __shfl_sync(0xffffffffu, base_pos, __ffs(m) - 1);
            int mypos = base_pos + __popc(m & lmask_lt);
            if (p && mypos < CAP) cand[mypos] = key[r];
        }
    }
    __syncthreads();

    // parallel rank-select: rank = #cand smaller (keys unique).
    int cnt = min(scnt, CAP);
    for (int i = t; i < cnt; i += 256) {
        unsigned long long k = cand[i];
        int rk = 0;
        for (int j = 0; j < cnt; j++)            // broadcast LDS.64 per j
            rk += (cand[j] < k) ? 1 : 0;
        if (rk < KNB) {
            int jm = (int)(unsigned)k;
            g_Eidx[row*KNB + rk] = jm;
            g_Dsel[row*KNB + rk] = __uint_as_float((unsigned)(k >> 32));
            if (outIdxF) outIdxF[row*KNB + rk] = (float)jm;
        }
    }
}

// ============================================================
// Kernel 3: edge features (16 RBF banks) -> bf16 hi/lo in global
// exp via FMA-pipe polynomial (no MUFU).
// ============================================================
__global__ __launch_bounds__(128) void feat_kernel(
    const float* __restrict__ X,
    const int*   __restrict__ ridx,
    const int*   __restrict__ chain)
{
    int row = blockIdx.x;
    int b   = row / LSZ;
    int t   = threadIdx.x;

    __shared__ float ia[4][3];
    __shared__ float ja[KNB][4][3];
    __shared__ int   jidx[KNB];
    __shared__ float dsel[KNB];
    __shared__ float dist[KNB][16];     // [0]=dsel, [1..15]=pair dists

    if (t < KNB) { jidx[t] = g_Eidx[row*KNB + t]; dsel[t] = g_Dsel[row*KNB + t]; }
    if (t >= 32 && t < 41) { int r = t - 32; ia[r/3][r%3] = X[row*12 + r]; }
    if (t >= 64 && t < 67) { ia[3][t-64] = g_Cb[row*3 + (t-64)]; }
    __syncthreads();

    for (int s = t; s < KNB*12; s += 128) {
        int k = s / 12, r = s % 12;
        int j = jidx[k];
        if (r < 9) ja[k][r/3][r%3] = X[(b*LSZ + j)*12 + r];
        else       ja[k][3][r-9]   = g_Cb[(b*LSZ + j)*3 + (r-9)];
    }
    if (t < KNB) {
        int j = jidx[t];
        int off  = ridx[row] - ridx[b*LSZ + j];
        int same = (chain[row] == chain[b*LSZ + j]);
        g_Dcode[row*KNB + t] = same ? min(max(off + MAXREL, 0), 2*MAXREL)
                                    : (2*MAXREL + 1);
        dist[t][0] = dsel[t];
    }
    __syncthreads();

    for (int s = t; s < KNB*16; s += 128) {
        int k = s >> 4, p = s & 15;
        if (p < 15) {
            int a = c_PA[p], bb = c_PB[p];
            float dx = ia[a][0] - ja[k][bb][0];
            float dy = ia[a][1] - ja[k][bb][1];
            float dz = ia[a][2] - ja[k][bb][2];
            dist[k][p+1] = sqrtf(dx*dx + dy*dy + dz*dz + 1e-6f);
        }
    }
    __syncthreads();

    // 256 channels per edge, emitted as 128 bf16x2 pairs (hi + lo)
    size_t base = (size_t)row * KNB * 128;
    for (int s = t; s < KNB*128; s += 128) {
        int k  = s >> 7;          // neighbor
        int pr = s & 127;         // pair index: channels 2pr, 2pr+1
        int c0 = pr*2, c1 = c0 + 1;
        float d0 = dist[k][c0 >> 4];
        float d1 = dist[k][c1 >> 4];
        float mu0 = 2.0f + (float)(c0 & 15) * (20.0f/15.0f);
        float mu1 = 2.0f + (float)(c1 & 15) * (20.0f/15.0f);
        float z0 = (d0 - mu0) * 0.8f;
        float z1 = (d1 - mu1) * 0.8f;
        float v0 = exp_neg(z0*z0);
        float v1 = exp_neg(z1*z1);
        __nv_bfloat16 h0 = __float2bfloat16(v0), h1 = __float2bfloat16(v1);
        float l0 = v0 - __bfloat162float(h0);
        float l1 = v1 - __bfloat162float(h1);
        g_Fh[base + s] = pack_bf16x2(h0, h1);
        g_Fl[base + s] = pack_bf16x2(__float2bfloat16(l0), __float2bfloat16(l1));
    }
}

// ============================================================
// Kernel 4: HMMA GEMM [128 edges x 256] @ [256 x 128] + Tpos +
// per-edge layernorm. 512 threads = 16 warps; warp (mh,nq) owns a
// 32x32 C tile. bf16 hi/lo split, 3 mma terms, fp32 accum.
// ============================================================
__global__ __launch_bounds__(512, 1) void gemm_kernel(
    const float* __restrict__ gamma,
    const float* __restrict__ beta,
    float*       __restrict__ outE)
{
    __shared__ __align__(16) __nv_bfloat16 Ah[128][ASTRIDE];
    __shared__ __align__(16) __nv_bfloat16 Al[128][ASTRIDE];
    __shared__ float rowsum[128], rowsq[128], smu[128], sinv[128];

    int t = threadIdx.x, lane = t & 31, w = t >> 5;
    int mh = w >> 2, nq = w & 3;         // warp tile: rows mh*32+, cols nq*32+
    int m0 = blockIdx.x * 128;
    int g  = lane >> 2, tg = lane & 3;

    if (t < 128) { rowsum[t] = 0.f; rowsq[t] = 0.f; }

    float C[2][4][4];
    #pragma unroll
    for (int mf = 0; mf < 2; mf++)
        #pragma unroll
        for (int nf = 0; nf < 4; nf++)
            #pragma unroll
            for (int i = 0; i < 4; i++) C[mf][nf][i] = 0.f;

    for (int kc = 0; kc < 4; kc++) {
        __syncthreads();
        // stage A chunk: 128 rows x 64 bf16 (hi + lo)
        #pragma unroll
        for (int u = 0; u < 4; u++) {
            int idx = t + 512*u;               // 0..2047
            int e = idx >> 4, un = idx & 15;
            size_t goff = (size_t)(m0 + e)*128 + kc*32 + un*2;
            uint2 vh = *reinterpret_cast<const uint2*>(&g_Fh[goff]);
            uint2 vl = *reinterpret_cast<const uint2*>(&g_Fl[goff]);
            *reinterpret_cast<uint2*>(&Ah[e][un*4]) = vh;
            *reinterpret_cast<uint2*>(&Al[e][un*4]) = vl;
        }
        __syncthreads();

        #pragma unroll
        for (int ks = 0; ks < 4; ks++) {
            uint2 bh[4], bl[4];
            int ksg = kc*4 + ks;
            #pragma unroll
            for (int nf = 0; nf < 4; nf++) {
                int gidx = (ksg*16 + nq*4 + nf)*32 + lane;
                bh[nf] = g_WfH[gidx];
                bl[nf] = g_WfL[gidx];
            }
            #pragma unroll
            for (int mf = 0; mf < 2; mf++) {
                int rr = mh*32 + mf*16 + (lane & 15);
                int cc = ks*16 + 8*(lane >> 4);
                uint32_t ah[4], al[4];
                ldsm_x4(ah, smem_to_u32(&Ah[rr][cc]));
                ldsm_x4(al, smem_to_u32(&Al[rr][cc]));
                #pragma unroll
                for (int nf = 0; nf < 4; nf++) {
                    mma_bf16(C[mf][nf], ah, reinterpret_cast<uint32_t*>(&bh[nf]));
                    mma_bf16(C[mf][nf], ah, reinterpret_cast<uint32_t*>(&bl[nf]));
                    mma_bf16(C[mf][nf], al, reinterpret_cast<uint32_t*>(&bh[nf]));
                }
            }
        }
    }

    // ---- epilogue: +Tpos, row sums (quad shfl + smem atomics) ----
    #pragma unroll
    for (int mf = 0; mf < 2; mf++) {
        int r0 = mh*32 + mf*16 + g;          // local rows r0, r0+8
        int dc0 = g_Dcode[m0 + r0];
        int dc1 = g_Dcode[m0 + r0 + 8];
        float s0 = 0.f, q0 = 0.f, s1 = 0.f, q1 = 0.f;
        #pragma unroll
        for (int nf = 0; nf < 4; nf++) {
            int col = nq*32 + nf*8 + tg*2;
            float2 t0 = *reinterpret_cast<const float2*>(&g_Tpos[dc0*NOUT + col]);
            float2 t1 = *reinterpret_cast<const float2*>(&g_Tpos[dc1*NOUT + col]);
            C[mf][nf][0] += t0.x;  C[mf][nf][1] += t0.y;
            C[mf][nf][2] += t1.x;  C[mf][nf][3] += t1.y;
            s0 += C[mf][nf][0] + C[mf][nf][1];
            q0 += C[mf][nf][0]*C[mf][nf][0] + C[mf][nf][1]*C[mf][nf][1];
            s1 += C[mf][nf][2] + C[mf][nf][3];
            q1 += C[mf][nf][2]*C[mf][nf][2] + C[mf][nf][3]*C[mf][nf][3];
        }
        s0 += __shfl_xor_sync(0xffffffffu, s0, 1);
        s0 += __shfl_xor_sync(0xffffffffu, s0, 2);
        q0 += __shfl_xor_sync(0xffffffffu, q0, 1);
        q0 += __shfl_xor_sync(0xffffffffu, q0, 2);
        s1 += __shfl_xor_sync(0xffffffffu, s1, 1);
        s1 += __shfl_xor_sync(0xffffffffu, s1, 2);
        q1 += __shfl_xor_sync(0xffffffffu, q1, 1);
        q1 += __shfl_xor_sync(0xffffffffu, q1, 2);
        if (tg == 0) {
            atomicAdd(&rowsum[r0],     s0);
            atomicAdd(&rowsq [r0],     q0);
            atomicAdd(&rowsum[r0 + 8], s1);
            atomicAdd(&rowsq [r0 + 8], q1);
        }
    }
    __syncthreads();
    if (t < 128) {
        float mu  = rowsum[t] * (1.0f/NOUT);
        float var = fmaxf(rowsq[t] * (1.0f/NOUT) - mu*mu, 0.0f);
        smu[t]  = mu;
        sinv[t] = rsqrtf(var + 1e-5f);
    }
    __syncthreads();

    #pragma unroll
    for (int mf = 0; mf < 2; mf++) {
        int r0 = mh*32 + mf*16 + g;
        float mu0 = smu[r0],   iv0 = sinv[r0];
        float mu1 = smu[r0+8], iv1 = sinv[r0+8];
        #pragma unroll
        for (int nf = 0; nf < 4; nf++) {
            int col = nq*32 + nf*8 + tg*2;
            float2 gm = *reinterpret_cast<const float2*>(&gamma[col]);
            float2 bt = *reinterpret_cast<const float2*>(&beta [col]);
            float2 o0, o1;
            o0.x = (C[mf][nf][0] - mu0)*iv0*gm.x + bt.x;
            o0.y = (C[mf][nf][1] - mu0)*iv0*gm.y + bt.y;
            o1.x = (C[mf][nf][2] - mu1)*iv1*gm.x + bt.x;
            o1.y = (C[mf][nf][3] - mu1)*iv1*gm.y + bt.y;
            *reinterpret_cast<float2*>(&outE[(size_t)(m0 + r0    )*NOUT + col]) = o0;
            *reinterpret_cast<float2*>(&outE[(size_t)(m0 + r0 + 8)*NOUT + col]) = o1;
        }
    }
}

// ============================================================
extern "C" void kernel_launch(void* const* d_in, const int* in_sizes, int n_in,
                              void* d_out, int out_size)
{
    const float* X      = (const float*)d_in[0];
    const float* mask   = (const float*)d_in[1];
    const int*   ridx   = (const int*)  d_in[2];
    const int*   chain  = (const int*)  d_in[3];
    const float* W_pos  = (const float*)d_in[4];
    const float* b_pos  = (const float*)d_in[5];
    const float* W_edge = (const float*)d_in[6];
    const float* gamma  = (const float*)d_in[7];
    const float* beta   = (const float*)d_in[8];

    float* outE = (float*)d_out;
    long long esz = (long long)NEDGE*NOUT;           // 31,457,280
    float* outIdxF = ((long long)out_size > esz) ? (outE + esz) : nullptr;

    tpos_kernel<<<NDC, NOUT>>>(W_pos, b_pos, W_edge);
    wprep_kernel<<<32, 256>>>(W_edge);
    cb_kernel  <<<(BSZ*LSZ + 255)/256, 256>>>(X, mask);
    topk_kernel<<<BSZ*LSZ, 256>>>(outIdxF);
    feat_kernel<<<BSZ*LSZ, 128>>>(X, ridx, chain);
    gemm_kernel<<<MTILES, 512>>>(gamma, beta, outE);
}

// round 16
// speedup vs baseline: 1.1250x; 1.1250x over previous
#include <cuda_runtime.h>
#include <cuda_bf16.h>
#include <cstdint>

// Problem constants (shapes fixed by setup_inputs)
#define BSZ   4
#define LSZ   2048
#define KNB   30      // TOP_K
#define NRB   256     // 16 banks * 16 rbf channels (positional via table)
#define NOUT  128
#define MAXREL 32
#define NDC   66      // dcode values: 0..64 same-chain, 65 cross-chain
#define NEDGE (BSZ*LSZ*KNB)     // 245760
#define MTILES (NEDGE/128)      // 1920 (exact)
#define ASTRIDE 72              // smem A row stride in bf16 (144B, 16B-aligned)
#define NBUCK 2048              // topk histogram buckets (float bits >> 20)
#define CAP   512               // candidate buffer bound

// gemm dynamic smem layout (double-buffered A tiles)
#define SMEM_AH   0
#define SMEM_AL   36864                      // 2*128*ASTRIDE*2 bytes
#define SMEM_FLT  73728                      // rowsum/rowsq/smu/sinv
#define SMEM_GEMM (SMEM_FLT + 4*128*4)       // 75776

// -------- device scratch (no cudaMalloc allowed) --------
__device__ float    g_Cb  [BSZ*LSZ*3];
__device__ float4   g_C4  [BSZ*LSZ];           // (Cx,Cy,Cz,mask) packed
__device__ int      g_Eidx[NEDGE];
__device__ float    g_Dsel[NEDGE];
__device__ int      g_Dcode[NEDGE];
__device__ float    g_Tpos[NDC*NOUT];          // (W_pos[d]+b_pos) @ W_edge[0:16]
__device__ uint32_t g_Fh[(size_t)NEDGE*128];   // features hi, bf16x2 pairs
__device__ uint32_t g_Fl[(size_t)NEDGE*128];   // features lo
__device__ uint2    g_WfH[16*16*32];           // W hi, B-fragment layout [ks][nf][lane]
__device__ uint2    g_WfL[16*16*32];           // W lo

// pair tables: dist(A_atom of residue i, B_atom of residue j)
// atom codes: 0=N, 1=C, 2=Ca, 3=Cb(virtual)
__constant__ int c_PA[15] = {0,2,3,1,1,1,0,0,3,0,2,3,2,3,2};
__constant__ int c_PB[15] = {0,2,3,0,2,3,2,3,2,1,1,1,0,0,3};

// ---------- helpers ----------
__device__ __forceinline__ uint32_t pack_bf16x2(__nv_bfloat16 lo, __nv_bfloat16 hi) {
    uint32_t l = (uint32_t)__bfloat16_as_ushort(lo);
    uint32_t h = (uint32_t)__bfloat16_as_ushort(hi);
    return l | (h << 16);
}
__device__ __forceinline__ uint32_t smem_to_u32(const void* p) {
    uint32_t a;
    asm("{ .reg .u64 t; cvta.to.shared.u64 t, %1; cvt.u32.u64 %0, t; }"
        : "=r"(a) : "l"(p));
    return a;
}
__device__ __forceinline__ void ldsm_x4(uint32_t* r, uint32_t addr) {
    asm volatile("ldmatrix.sync.aligned.m8n8.x4.shared.b16 {%0,%1,%2,%3}, [%4];"
        : "=r"(r[0]), "=r"(r[1]), "=r"(r[2]), "=r"(r[3]) : "r"(addr));
}
__device__ __forceinline__ void mma_bf16(float* c, const uint32_t* a,
                                         const uint32_t* b) {
    asm volatile(
        "mma.sync.aligned.m16n8k16.row.col.f32.bf16.bf16.f32 "
        "{%0,%1,%2,%3}, {%4,%5,%6,%7}, {%8,%9}, {%0,%1,%2,%3};"
        : "+f"(c[0]), "+f"(c[1]), "+f"(c[2]), "+f"(c[3])
        : "r"(a[0]), "r"(a[1]), "r"(a[2]), "r"(a[3]), "r"(b[0]), "r"(b[1]));
}
__device__ __forceinline__ void cp_async8(uint32_t smem_dst, const void* gsrc) {
    asm volatile("cp.async.ca.shared.global [%0], [%1], 8;"
        :: "r"(smem_dst), "l"(__cvta_generic_to_global(gsrc)) : "memory");
}
// exp(-u), u >= 0, FMA/ALU pipes only (no MUFU). ~1e-7 rel.
__device__ __forceinline__ float exp_neg(float u) {
    float t = fmaxf(-u * 1.4426950408889634f, -150.0f);
    float k = rintf(t);
    float f = t - k;
    float p =        1.5403530393e-4f;
    p = fmaf(p, f, 1.3333558146e-3f);
    p = fmaf(p, f, 9.6181291076e-3f);
    p = fmaf(p, f, 5.5504108665e-2f);
    p = fmaf(p, f, 2.4022650696e-1f);
    p = fmaf(p, f, 6.9314718056e-1f);
    p = fmaf(p, f, 1.0f);
    int ki = (int)k;
    int k1 = ki >> 1, k2 = ki - k1;        // two-step scale, no underflow wrap
    float s1 = __int_as_float((k1 + 127) << 23);
    float s2 = __int_as_float((k2 + 127) << 23);
    return p * s1 * s2;
}

// ============================================================
// Kernel 0a: positional projection table
// ============================================================
__global__ void tpos_kernel(const float* __restrict__ W_pos,
                            const float* __restrict__ b_pos,
                            const float* __restrict__ W_edge)
{
    int d = blockIdx.x, t = threadIdx.x;
    float acc = 0.f;
    #pragma unroll
    for (int f = 0; f < 16; f++)
        acc = fmaf(W_pos[d*16 + f] + b_pos[f], W_edge[f*NOUT + t], acc);
    g_Tpos[d*NOUT + t] = acc;
}

// Kernel 0b: W -> bf16 hi/lo in exact mma.sync B-fragment order.
__global__ void wprep_kernel(const float* __restrict__ W_edge)
{
    int idx = blockIdx.x*256 + threadIdx.x;      // 8192 frags
    int lane = idx & 31, nfg = (idx >> 5) & 15, ks = idx >> 9;
    int n = nfg*8 + (lane >> 2);
    int k = ks*16 + 2*(lane & 3);
    float w[4];
    w[0] = W_edge[(16 + k    )*NOUT + n];
    w[1] = W_edge[(16 + k + 1)*NOUT + n];
    w[2] = W_edge[(16 + k + 8)*NOUT + n];
    w[3] = W_edge[(16 + k + 9)*NOUT + n];
    __nv_bfloat16 h[4]; float l[4];
    #pragma unroll
    for (int i = 0; i < 4; i++) {
        h[i] = __float2bfloat16(w[i]);
        l[i] = w[i] - __bfloat162float(h[i]);
    }
    uint2 uh, ul;
    uh.x = pack_bf16x2(h[0], h[1]);
    uh.y = pack_bf16x2(h[2], h[3]);
    ul.x = pack_bf16x2(__float2bfloat16(l[0]), __float2bfloat16(l[1]));
    ul.y = pack_bf16x2(__float2bfloat16(l[2]), __float2bfloat16(l[3]));
    g_WfH[idx] = uh;
    g_WfL[idx] = ul;
}

// ============================================================
// Kernel 1: virtual C-beta + packed (C,mask) float4
// ============================================================
__global__ void cb_kernel(const float* __restrict__ X,
                          const float* __restrict__ mask)
{
    int i = blockIdx.x * 256 + threadIdx.x;
    if (i >= BSZ*LSZ) return;
    const float* x = &X[i*12];
    float Nx=x[0],  Ny=x[1],  Nz=x[2];
    float Cx=x[3],  Cy=x[4],  Cz=x[5];
    float Ax=x[6],  Ay=x[7],  Az=x[8];
    float bx=Ax-Nx, by=Ay-Ny, bz=Az-Nz;
    float cx=Cx-Ax, cy=Cy-Ay, cz=Cz-Az;
    float ax = by*cz - bz*cy;
    float ay = bz*cx - bx*cz;
    float az = bx*cy - by*cx;
    g_Cb[i*3+0] = -0.58273431f*ax + 0.56802827f*bx - 0.54067466f*cx + Ax;
    g_Cb[i*3+1] = -0.58273431f*ay + 0.56802827f*by - 0.54067466f*cy + Ay;
    g_Cb[i*3+2] = -0.58273431f*az + 0.56802827f*bz - 0.54067466f*cz + Az;
    g_C4[i] = make_float4(Cx, Cy, Cz, mask[i]);
}

// ============================================================
// Kernel 2: masked pairwise C-C distances + EXACT top-30 via
// histogram select + PARALLEL RANK placement. (R14-exact version:
// plain atomics — warp-aggregation measured slower in R15.)
// ============================================================
__global__ __launch_bounds__(256) void topk_kernel(float* __restrict__ outIdxF)
{
    int row = blockIdx.x;
    int b   = row / LSZ;
    int t   = threadIdx.x;
    int warp = t >> 5, lane = t & 31;

    __shared__ float wmax[8];
    __shared__ float sDmax;
    __shared__ uint32_t hist[NBUCK];
    __shared__ int sB;
    __shared__ int scnt;
    __shared__ unsigned long long cand[CAP];

    float4 me = g_C4[row];
    float mi = me.w;

    float dv[8], m2v[8];
    float lmax = 0.f;
    #pragma unroll
    for (int r = 0; r < 8; r++) {
        int j = t + r*256;
        float4 pj = g_C4[b*LSZ + j];
        float dx = me.x-pj.x, dy = me.y-pj.y, dz = me.z-pj.z;
        float d  = sqrtf(dx*dx + dy*dy + dz*dz + 1e-6f);
        float m2 = mi * pj.w;
        dv[r]  = m2 * d;
        m2v[r] = m2;
        lmax = fmaxf(lmax, dv[r]);
    }
    #pragma unroll
    for (int o = 16; o > 0; o >>= 1)
        lmax = fmaxf(lmax, __shfl_xor_sync(0xffffffffu, lmax, o));
    if (lane == 0) wmax[warp] = lmax;
    // zero histogram + counter while the max reduction settles
    #pragma unroll
    for (int h = 0; h < NBUCK/256; h++) hist[t + h*256] = 0;
    if (t == 0) scnt = 0;
    __syncthreads();
    if (t == 0) {
        float m = wmax[0];
        for (int w = 1; w < 8; w++) m = fmaxf(m, wmax[w]);
        sDmax = m;
    }
    __syncthreads();
    float Dmax = sDmax;

    unsigned long long key[8];
    #pragma unroll
    for (int r = 0; r < 8; r++) {
        float adj = dv[r] + (1.0f - m2v[r]) * Dmax;      // D_adjust
        key[r] = ((unsigned long long)__float_as_uint(adj) << 32)
               | (unsigned)(t + r*256);
        atomicAdd(&hist[(unsigned)(key[r] >> 52)], 1u);
    }
    __syncthreads();

    // warp 0: find threshold bucket B (cum count reaches KNB)
    if (warp == 0) {
        int base = lane * (NBUCK/32);
        int s = 0;
        #pragma unroll 8
        for (int c = 0; c < NBUCK/32; c++) s += (int)hist[base + c];
        int pre = s;
        #pragma unroll
        for (int o = 1; o < 32; o <<= 1) {
            int v = __shfl_up_sync(0xffffffffu, pre, o);
            if (lane >= o) pre += v;
        }
        pre -= s;                         // exclusive prefix
        if (pre < KNB && pre + s >= KNB) {
            int acc = pre, Bq = base + NBUCK/32 - 1;
            for (int c = 0; c < NBUCK/32; c++) {
                acc += (int)hist[base + c];
                if (acc >= KNB) { Bq = base + c; break; }
            }
            sB = Bq;
        }
    }
    __syncthreads();

    // compact candidates (all keys in buckets <= B; superset of top-30)
    int B = sB;
    #pragma unroll
    for (int r = 0; r < 8; r++) {
        if ((int)(unsigned)(key[r] >> 52) <= B) {
            int p = atomicAdd(&scnt, 1);
            if (p < CAP) cand[p] = key[r];
        }
    }
    __syncthreads();

    // parallel rank-select: rank = #cand smaller (keys unique).
    int cnt = min(scnt, CAP);
    for (int i = t; i < cnt; i += 256) {
        unsigned long long k = cand[i];
        int rk = 0;
        for (int j = 0; j < cnt; j++)            // broadcast LDS.64 per j
            rk += (cand[j] < k) ? 1 : 0;
        if (rk < KNB) {
            int jm = (int)(unsigned)k;
            g_Eidx[row*KNB + rk] = jm;
            g_Dsel[row*KNB + rk] = __uint_as_float((unsigned)(k >> 32));
            if (outIdxF) outIdxF[row*KNB + rk] = (float)jm;
        }
    }
}

// ============================================================
// Kernel 3: edge features (16 RBF banks) -> bf16 hi/lo in global
// exp via FMA-pipe polynomial (no MUFU).
// ============================================================
__global__ __launch_bounds__(128) void feat_kernel(
    const float* __restrict__ X,
    const int*   __restrict__ ridx,
    const int*   __restrict__ chain)
{
    int row = blockIdx.x;
    int b   = row / LSZ;
    int t   = threadIdx.x;

    __shared__ float ia[4][3];
    __shared__ float ja[KNB][4][3];
    __shared__ int   jidx[KNB];
    __shared__ float dsel[KNB];
    __shared__ float dist[KNB][16];     // [0]=dsel, [1..15]=pair dists

    if (t < KNB) { jidx[t] = g_Eidx[row*KNB + t]; dsel[t] = g_Dsel[row*KNB + t]; }
    if (t >= 32 && t < 41) { int r = t - 32; ia[r/3][r%3] = X[row*12 + r]; }
    if (t >= 64 && t < 67) { ia[3][t-64] = g_Cb[row*3 + (t-64)]; }
    __syncthreads();

    for (int s = t; s < KNB*12; s += 128) {
        int k = s / 12, r = s % 12;
        int j = jidx[k];
        if (r < 9) ja[k][r/3][r%3] = X[(b*LSZ + j)*12 + r];
        else       ja[k][3][r-9]   = g_Cb[(b*LSZ + j)*3 + (r-9)];
    }
    if (t < KNB) {
        int j = jidx[t];
        int off  = ridx[row] - ridx[b*LSZ + j];
        int same = (chain[row] == chain[b*LSZ + j]);
        g_Dcode[row*KNB + t] = same ? min(max(off + MAXREL, 0), 2*MAXREL)
                                    : (2*MAXREL + 1);
        dist[t][0] = dsel[t];
    }
    __syncthreads();

    for (int s = t; s < KNB*16; s += 128) {
        int k = s >> 4, p = s & 15;
        if (p < 15) {
            int a = c_PA[p], bb = c_PB[p];
            float dx = ia[a][0] - ja[k][bb][0];
            float dy = ia[a][1] - ja[k][bb][1];
            float dz = ia[a][2] - ja[k][bb][2];
            dist[k][p+1] = sqrtf(dx*dx + dy*dy + dz*dz + 1e-6f);
        }
    }
    __syncthreads();

    // 256 channels per edge, emitted as 128 bf16x2 pairs (hi + lo)
    size_t base = (size_t)row * KNB * 128;
    for (int s = t; s < KNB*128; s += 128) {
        int k  = s >> 7;          // neighbor
        int pr = s & 127;         // pair index: channels 2pr, 2pr+1
        int c0 = pr*2, c1 = c0 + 1;
        float d0 = dist[k][c0 >> 4];
        float d1 = dist[k][c1 >> 4];
        float mu0 = 2.0f + (float)(c0 & 15) * (20.0f/15.0f);
        float mu1 = 2.0f + (float)(c1 & 15) * (20.0f/15.0f);
        float z0 = (d0 - mu0) * 0.8f;
        float z1 = (d1 - mu1) * 0.8f;
        float v0 = exp_neg(z0*z0);
        float v1 = exp_neg(z1*z1);
        __nv_bfloat16 h0 = __float2bfloat16(v0), h1 = __float2bfloat16(v1);
        float l0 = v0 - __bfloat162float(h0);
        float l1 = v1 - __bfloat162float(h1);
        g_Fh[base + s] = pack_bf16x2(h0, h1);
        g_Fl[base + s] = pack_bf16x2(__float2bfloat16(l0), __float2bfloat16(l1));
    }
}

// ============================================================
// Kernel 4: HMMA GEMM [128 edges x 256] @ [256 x 128] + Tpos +
// per-edge layernorm. DOUBLE-BUFFERED A staging via cp.async:
// chunk kc+1 streams into the other buffer while kc computes,
// removing the 4x exposed staging latency of the serial version.
// ============================================================
__global__ __launch_bounds__(512, 1) void gemm_kernel(
    const float* __restrict__ gamma,
    const float* __restrict__ beta,
    float*       __restrict__ outE)
{
    extern __shared__ char dynsm[];
    __nv_bfloat16 (*Ah)[128][ASTRIDE] =
        reinterpret_cast<__nv_bfloat16 (*)[128][ASTRIDE]>(dynsm + SMEM_AH);
    __nv_bfloat16 (*Al)[128][ASTRIDE] =
        reinterpret_cast<__nv_bfloat16 (*)[128][ASTRIDE]>(dynsm + SMEM_AL);
    float* rowsum = reinterpret_cast<float*>(dynsm + SMEM_FLT);
    float* rowsq  = rowsum + 128;
    float* smu    = rowsum + 256;
    float* sinv   = rowsum + 384;

    int t = threadIdx.x, lane = t & 31, w = t >> 5;
    int mh = w >> 2, nq = w & 3;         // warp tile: rows mh*32+, cols nq*32+
    int m0 = blockIdx.x * 128;
    int g  = lane >> 2, tg = lane & 3;

    if (t < 128) { rowsum[t] = 0.f; rowsq[t] = 0.f; }

    float C[2][4][4];
    #pragma unroll
    for (int mf = 0; mf < 2; mf++)
        #pragma unroll
        for (int nf = 0; nf < 4; nf++)
            #pragma unroll
            for (int i = 0; i < 4; i++) C[mf][nf][i] = 0.f;

    // async stage of one 128x32-pair chunk (hi+lo) into buffer bf
    auto stage = [&](int kc, int bf) {
        #pragma unroll
        for (int u = 0; u < 4; u++) {
            int idx = t + 512*u;               // 0..2047
            int e = idx >> 4, un = idx & 15;
            size_t goff = (size_t)(m0 + e)*128 + kc*32 + un*2;
            cp_async8(smem_to_u32(&Ah[bf][e][un*4]), &g_Fh[goff]);
            cp_async8(smem_to_u32(&Al[bf][e][un*4]), &g_Fl[goff]);
        }
        asm volatile("cp.async.commit_group;" ::: "memory");
    };

    stage(0, 0);

    for (int kc = 0; kc < 4; kc++) {
        asm volatile("cp.async.wait_group 0;" ::: "memory");
        __syncthreads();                       // staged data visible; prior
                                               // compute done block-wide
        if (kc < 3) stage(kc + 1, (kc + 1) & 1);
        int bf = kc & 1;

        #pragma unroll
        for (int ks = 0; ks < 4; ks++) {
            uint2 bh[4], bl[4];
            int ksg = kc*4 + ks;
            #pragma unroll
            for (int nf = 0; nf < 4; nf++) {
                int gidx = (ksg*16 + nq*4 + nf)*32 + lane;
                bh[nf] = g_WfH[gidx];
                bl[nf] = g_WfL[gidx];
            }
            #pragma unroll
            for (int mf = 0; mf < 2; mf++) {
                int rr = mh*32 + mf*16 + (lane & 15);
                int cc = ks*16 + 8*(lane >> 4);
                uint32_t ah[4], al[4];
                ldsm_x4(ah, smem_to_u32(&Ah[bf][rr][cc]));
                ldsm_x4(al, smem_to_u32(&Al[bf][rr][cc]));
                #pragma unroll
                for (int nf = 0; nf < 4; nf++) {
                    mma_bf16(C[mf][nf], ah, reinterpret_cast<uint32_t*>(&bh[nf]));
                    mma_bf16(C[mf][nf], ah, reinterpret_cast<uint32_t*>(&bl[nf]));
                    mma_bf16(C[mf][nf], al, reinterpret_cast<uint32_t*>(&bh[nf]));
                }
            }
        }
    }

    // ---- epilogue: +Tpos, row sums (quad shfl + smem atomics) ----
    #pragma unroll
    for (int mf = 0; mf < 2; mf++) {
        int r0 = mh*32 + mf*16 + g;          // local rows r0, r0+8
        int dc0 = g_Dcode[m0 + r0];
        int dc1 = g_Dcode[m0 + r0 + 8];
        float s0 = 0.f, q0 = 0.f, s1 = 0.f, q1 = 0.f;
        #pragma unroll
        for (int nf = 0; nf < 4; nf++) {
            int col = nq*32 + nf*8 + tg*2;
            float2 t0 = *reinterpret_cast<const float2*>(&g_Tpos[dc0*NOUT + col]);
            float2 t1 = *reinterpret_cast<const float2*>(&g_Tpos[dc1*NOUT + col]);
            C[mf][nf][0] += t0.x;  C[mf][nf][1] += t0.y;
            C[mf][nf][2] += t1.x;  C[mf][nf][3] += t1.y;
            s0 += C[mf][nf][0] + C[mf][nf][1];
            q0 += C[mf][nf][0]*C[mf][nf][0] + C[mf][nf][1]*C[mf][nf][1];
            s1 += C[mf][nf][2] + C[mf][nf][3];
            q1 += C[mf][nf][2]*C[mf][nf][2] + C[mf][nf][3]*C[mf][nf][3];
        }
        s0 += __shfl_xor_sync(0xffffffffu, s0, 1);
        s0 += __shfl_xor_sync(0xffffffffu, s0, 2);
        q0 += __shfl_xor_sync(0xffffffffu, q0, 1);
        q0 += __shfl_xor_sync(0xffffffffu, q0, 2);
        s1 += __shfl_xor_sync(0xffffffffu, s1, 1);
        s1 += __shfl_xor_sync(0xffffffffu, s1, 2);
        q1 += __shfl_xor_sync(0xffffffffu, q1, 1);
        q1 += __shfl_xor_sync(0xffffffffu, q1, 2);
        if (tg == 0) {
            atomicAdd(&rowsum[r0],     s0);
            atomicAdd(&rowsq [r0],     q0);
            atomicAdd(&rowsum[r0 + 8], s1);
            atomicAdd(&rowsq [r0 + 8], q1);
        }
    }
    __syncthreads();
    if (t < 128) {
        float mu  = rowsum[t] * (1.0f/NOUT);
        float var = fmaxf(rowsq[t] * (1.0f/NOUT) - mu*mu, 0.0f);
        smu[t]  = mu;
        sinv[t] = rsqrtf(var + 1e-5f);
    }
    __syncthreads();

    #pragma unroll
    for (int mf = 0; mf < 2; mf++) {
        int r0 = mh*32 + mf*16 + g;
        float mu0 = smu[r0],   iv0 = sinv[r0];
        float mu1 = smu[r0+8], iv1 = sinv[r0+8];
        #pragma unroll
        for (int nf = 0; nf < 4; nf++) {
            int col = nq*32 + nf*8 + tg*2;
            float2 gm = *reinterpret_cast<const float2*>(&gamma[col]);
            float2 bt = *reinterpret_cast<const float2*>(&beta [col]);
            float2 o0, o1;
            o0.x = (C[mf][nf][0] - mu0)*iv0*gm.x + bt.x;
            o0.y = (C[mf][nf][1] - mu0)*iv0*gm.y + bt.y;
            o1.x = (C[mf][nf][2] - mu1)*iv1*gm.x + bt.x;
            o1.y = (C[mf][nf][3] - mu1)*iv1*gm.y + bt.y;
            *reinterpret_cast<float2*>(&outE[(size_t)(m0 + r0    )*NOUT + col]) = o0;
            *reinterpret_cast<float2*>(&outE[(size_t)(m0 + r0 + 8)*NOUT + col]) = o1;
        }
    }
}

// ============================================================
extern "C" void kernel_launch(void* const* d_in, const int* in_sizes, int n_in,
                              void* d_out, int out_size)
{
    const float* X      = (const float*)d_in[0];
    const float* mask   = (const float*)d_in[1];
    const int*   ridx   = (const int*)  d_in[2];
    const int*   chain  = (const int*)  d_in[3];
    const float* W_pos  = (const float*)d_in[4];
    const float* b_pos  = (const float*)d_in[5];
    const float* W_edge = (const float*)d_in[6];
    const float* gamma  = (const float*)d_in[7];
    const float* beta   = (const float*)d_in[8];

    float* outE = (float*)d_out;
    long long esz = (long long)NEDGE*NOUT;           // 31,457,280
    float* outIdxF = ((long long)out_size > esz) ? (outE + esz) : nullptr;

    static bool attr_set = false;
    if (!attr_set) {
        cudaFuncSetAttribute(gemm_kernel,
                             cudaFuncAttributeMaxDynamicSharedMemorySize,
                             SMEM_GEMM);
        attr_set = true;
    }

    tpos_kernel<<<NDC, NOUT>>>(W_pos, b_pos, W_edge);
    wprep_kernel<<<32, 256>>>(W_edge);
    cb_kernel  <<<(BSZ*LSZ + 255)/256, 256>>>(X, mask);
    topk_kernel<<<BSZ*LSZ, 256>>>(outIdxF);
    feat_kernel<<<BSZ*LSZ, 128>>>(X, ridx, chain);
    gemm_kernel<<<MTILES, 512, SMEM_GEMM>>>(gamma, beta, outE);
}